// round 1
// baseline (speedup 1.0000x reference)
#include <cuda_runtime.h>

#define BB 32
#define SS 128
#define KN 12
#define KC 10
#define DD 200
#define CC 45
#define FF (5*DD)      // 1000
#define TPB_TOK 4      // tokens per block in gemm kernel

__device__ float g_feat[BB*SS*DD];   // [B,S,D] scratch (3.2 MB)
__device__ float g_Wt[FF*CC];        // W transposed: [f, c]

// ---------------------------------------------------------------------------
// Kernel 0: transpose W [C, F] -> Wt [F, C] so the 45 c-lanes read contiguous
// ---------------------------------------------------------------------------
__global__ void transpose_W_kernel(const float* __restrict__ W) {
    int i = blockIdx.x * blockDim.x + threadIdx.x;
    if (i < FF * CC) {
        int f = i / CC;
        int c = i % CC;
        g_Wt[i] = W[c * FF + f];
    }
}

// ---------------------------------------------------------------------------
// Kernel 1: masked gather + mean  -> g_feat[b,s,:]
// One block per token (b*S+s), thread = d. Masked-out rows are never loaded.
// ---------------------------------------------------------------------------
__global__ void feat_kernel(const int* __restrict__ ngram_ids,
                            const int* __restrict__ ngram_mask,
                            const int* __restrict__ ctx_ids,
                            const int* __restrict__ ctx_mask,
                            const float* __restrict__ embed) {
    const int tok = blockIdx.x;         // b*S + s
    const int d = threadIdx.x;

    __shared__ int s_id[KN + KC];
    __shared__ int s_mk[KN + KC];

    if (threadIdx.x < KN) {
        s_id[threadIdx.x] = ngram_ids[tok * KN + threadIdx.x];
        s_mk[threadIdx.x] = ngram_mask[tok * KN + threadIdx.x];
    } else if (threadIdx.x < KN + KC) {
        int k = threadIdx.x - KN;
        s_id[threadIdx.x] = ctx_ids[tok * KC + k];
        s_mk[threadIdx.x] = ctx_mask[tok * KC + k];
    }
    __syncthreads();

    if (d >= DD) return;

    float acc = 0.0f;
    int cnt = 0;
    #pragma unroll
    for (int k = 0; k < KN + KC; k++) {
        if (s_mk[k]) {                       // uniform branch per k: skip load
            acc += embed[(long long)s_id[k] * DD + d];
            cnt++;
        }
    }
    float denom = cnt > 0 ? (float)cnt : 1.0f;
    g_feat[tok * DD + d] = acc / denom;
}

// ---------------------------------------------------------------------------
// Kernel 2: window-5 concat + linear.  Block = TPB_TOK tokens of one batch
// row; smem holds TPB_TOK+4 feat rows (zero halo at sequence edges).
// Thread (t, c): 1000-length dot of windowed feat against Wt column c.
// ---------------------------------------------------------------------------
__global__ void gemm_kernel(const float* __restrict__ bias,
                            float* __restrict__ out) {
    const int blk = blockIdx.x;
    const int b  = blk / (SS / TPB_TOK);
    const int s0 = (blk % (SS / TPB_TOK)) * TPB_TOK;

    __shared__ float sh[(TPB_TOK + 4) * DD];   // 6.4 KB

    for (int i = threadIdx.x; i < (TPB_TOK + 4) * DD; i += blockDim.x) {
        int r = i / DD;                 // 0..TPB_TOK+3
        int d = i % DD;
        int s = s0 - 2 + r;             // window halo of 2 each side
        sh[i] = (s >= 0 && s < SS) ? g_feat[(b * SS + s) * DD + d] : 0.0f;
    }
    __syncthreads();

    const int t = threadIdx.x / CC;
    const int c = threadIdx.x % CC;
    if (t >= TPB_TOK) return;

    float acc = bias[c];
    #pragma unroll
    for (int w = 0; w < 5; w++) {
        const float* sf = &sh[(t + w) * DD];
        const float* wp = &g_Wt[(w * DD) * CC + c];
        #pragma unroll 4
        for (int d = 0; d < DD; d++) {
            acc = fmaf(sf[d], wp[d * CC], acc);
        }
    }
    out[(b * SS + s0 + t) * CC + c] = acc;
}

// ---------------------------------------------------------------------------
// Launch. Inputs (metadata order):
// 0 ngram_ids [B,S,KN] i32, 1 ngram_mask [B,S,KN] i32,
// 2 ctx_ids [B,S,KC] i32, 3 ctx_mask [B,S,KC] i32,
// 4 embed [V,D] f32, 5 W [C,5D] f32, 6 b [C] f32.  Output [B,S,C] f32.
// ---------------------------------------------------------------------------
extern "C" void kernel_launch(void* const* d_in, const int* in_sizes, int n_in,
                              void* d_out, int out_size) {
    const int*   ngram_ids  = (const int*)d_in[0];
    const int*   ngram_mask = (const int*)d_in[1];
    const int*   ctx_ids    = (const int*)d_in[2];
    const int*   ctx_mask   = (const int*)d_in[3];
    const float* embed      = (const float*)d_in[4];
    const float* W          = (const float*)d_in[5];
    const float* bias       = (const float*)d_in[6];
    float* out = (float*)d_out;

    transpose_W_kernel<<<(FF * CC + 255) / 256, 256>>>(W);
    feat_kernel<<<BB * SS, 256>>>(ngram_ids, ngram_mask, ctx_ids, ctx_mask, embed);
    gemm_kernel<<<BB * SS / TPB_TOK, ((TPB_TOK * CC + 31) / 32) * 32>>>(bias, out);
}

// round 2
// speedup vs baseline: 1.6412x; 1.6412x over previous
#include <cuda_runtime.h>

#define BB 32
#define SS 128
#define KN 12
#define KC 10
#define DD 200
#define CC 45
#define CP 48                 // padded C (12 float4 groups)
#define FF (5*DD)             // 1000
#define GT 16                 // tokens per gemm block

#define FEAT_BLOCKS (BB*SS)                       // 4096
#define K1_THREADS 224
#define TR_ELEMS (FF*CP)                          // 48000
#define TR_BLOCKS ((TR_ELEMS + K1_THREADS - 1) / K1_THREADS)   // 215

__device__ float g_feat[BB*SS*DD];    // [B*S, D] scratch
__device__ float g_Wt[FF*CP];         // W transposed+padded: [k, 48]

// ---------------------------------------------------------------------------
// Kernel 1: (a) masked gather + mean -> g_feat, (b) transpose W -> g_Wt.
// Fused into one grid so the tiny transpose overlaps the gather.
// ---------------------------------------------------------------------------
__global__ void feat_tr_kernel(const int* __restrict__ ngram_ids,
                               const int* __restrict__ ngram_mask,
                               const int* __restrict__ ctx_ids,
                               const int* __restrict__ ctx_mask,
                               const float* __restrict__ embed,
                               const float* __restrict__ W) {
    if (blockIdx.x >= FEAT_BLOCKS) {
        // ---- transpose part: coalesced read of W[c, :], scatter to g_Wt ----
        int idx = (blockIdx.x - FEAT_BLOCKS) * K1_THREADS + threadIdx.x;
        if (idx < TR_ELEMS) {
            int c = idx / FF;
            int k = idx - c * FF;
            g_Wt[k * CP + c] = (c < CC) ? W[c * FF + k] : 0.0f;
        }
        return;
    }

    const int tok = blockIdx.x;   // b*S + s
    const int d = threadIdx.x;

    __shared__ int s_id[KN + KC];
    __shared__ int s_mk[KN + KC];

    if (threadIdx.x < KN) {
        s_id[threadIdx.x] = ngram_ids[tok * KN + threadIdx.x];
        s_mk[threadIdx.x] = ngram_mask[tok * KN + threadIdx.x];
    } else if (threadIdx.x < KN + KC) {
        int k = threadIdx.x - KN;
        s_id[threadIdx.x] = ctx_ids[tok * KC + k];
        s_mk[threadIdx.x] = ctx_mask[tok * KC + k];
    }
    __syncthreads();

    if (d >= DD) return;

    float acc = 0.0f;
    int cnt = 0;
    #pragma unroll
    for (int k = 0; k < KN + KC; k++) {
        if (s_mk[k]) {                       // warp-uniform: masked rows never loaded
            acc += embed[(long long)s_id[k] * DD + d];
            cnt++;
        }
    }
    float denom = cnt > 0 ? (float)cnt : 1.0f;
    g_feat[tok * DD + d] = acc / denom;
}

// ---------------------------------------------------------------------------
// Kernel 2: window-5 linear as a register-tiled FFMA GEMM.
// Block: 16 tokens x 48 c, 192 threads. Thread (tg, cg): 1 token x 4 c.
// Warp lanes = 16 tokens x 2 c-groups -> B LDS near-broadcast, A LDS 16-way.
// k split into 5 chunks of 200 (one window position each): A row is fixed
// per chunk; B chunk (200x48 = 38.4KB) staged in smem.
// Per 4-k step: 1 LDS.128 (A) + 4 LDS.128 (B) + 16 FFMA.
// ---------------------------------------------------------------------------
__global__ void __launch_bounds__(192) gemm_kernel(const float* __restrict__ bias,
                                                   float* __restrict__ out) {
    __shared__ float shA[(GT + 4) * DD];     // 16000 B
    __shared__ float shB[DD * CP];           // 38400 B

    const int tokBase = blockIdx.x * GT;
    const int b  = tokBase / SS;
    const int s0 = tokBase % SS;             // multiple of 16; window stays in row b

    // stage A rows s0-2 .. s0+GT+1 (zero halo at sequence edges), float4
    const float4* gf4 = (const float4*)g_feat;
    float4* shA4 = (float4*)shA;
    for (int i = threadIdx.x; i < (GT + 4) * (DD / 4); i += blockDim.x) {
        int r  = i / (DD / 4);
        int dv = i - r * (DD / 4);
        int s  = s0 - 2 + r;
        float4 v = make_float4(0.f, 0.f, 0.f, 0.f);
        if (s >= 0 && s < SS) v = gf4[(b * SS + s) * (DD / 4) + dv];
        shA4[i] = v;
    }

    const int tg = threadIdx.x & (GT - 1);   // token in tile
    const int cg = threadIdx.x >> 4;         // 0..11 -> c0 = 4*cg
    const int c0 = cg * 4;

    float acc0 = bias[c0];                                  // c0 <= 44 always
    float acc1 = (c0 + 1 < CC) ? bias[c0 + 1] : 0.f;
    float acc2 = (c0 + 2 < CC) ? bias[c0 + 2] : 0.f;
    float acc3 = (c0 + 3 < CC) ? bias[c0 + 3] : 0.f;

    const float4* Wt4 = (const float4*)g_Wt;
    float4* shB4 = (float4*)shB;

    #pragma unroll
    for (int w = 0; w < 5; w++) {
        __syncthreads();
        // stage B chunk for this window position: rows w*200 .. w*200+199
        for (int i = threadIdx.x; i < DD * (CP / 4); i += blockDim.x)
            shB4[i] = Wt4[(w * DD) * (CP / 4) + i];
        __syncthreads();

        const float4* aRow = (const float4*)&shA[(tg + w) * DD];
        #pragma unroll 10
        for (int dq = 0; dq < DD / 4; dq++) {
            float4 a  = aRow[dq];
            float4 b0 = shB4[(dq * 4 + 0) * (CP / 4) + cg];
            float4 b1 = shB4[(dq * 4 + 1) * (CP / 4) + cg];
            float4 b2 = shB4[(dq * 4 + 2) * (CP / 4) + cg];
            float4 b3 = shB4[(dq * 4 + 3) * (CP / 4) + cg];
            acc0 = fmaf(a.x, b0.x, fmaf(a.y, b1.x, fmaf(a.z, b2.x, fmaf(a.w, b3.x, acc0))));
            acc1 = fmaf(a.x, b0.y, fmaf(a.y, b1.y, fmaf(a.z, b2.y, fmaf(a.w, b3.y, acc1))));
            acc2 = fmaf(a.x, b0.z, fmaf(a.y, b1.z, fmaf(a.z, b2.z, fmaf(a.w, b3.z, acc2))));
            acc3 = fmaf(a.x, b0.w, fmaf(a.y, b1.w, fmaf(a.z, b2.w, fmaf(a.w, b3.w, acc3))));
        }
    }

    float* o = out + (long long)(tokBase + tg) * CC;
    o[c0] = acc0;
    if (c0 + 1 < CC) o[c0 + 1] = acc1;
    if (c0 + 2 < CC) o[c0 + 2] = acc2;
    if (c0 + 3 < CC) o[c0 + 3] = acc3;
}

// ---------------------------------------------------------------------------
// Inputs (metadata order):
// 0 ngram_ids [B,S,KN] i32, 1 ngram_mask, 2 ctx_ids [B,S,KC] i32, 3 ctx_mask,
// 4 embed [V,D] f32, 5 W [C,5D] f32, 6 b [C] f32.  Output [B,S,C] f32.
// ---------------------------------------------------------------------------
extern "C" void kernel_launch(void* const* d_in, const int* in_sizes, int n_in,
                              void* d_out, int out_size) {
    const int*   ngram_ids  = (const int*)d_in[0];
    const int*   ngram_mask = (const int*)d_in[1];
    const int*   ctx_ids    = (const int*)d_in[2];
    const int*   ctx_mask   = (const int*)d_in[3];
    const float* embed      = (const float*)d_in[4];
    const float* W          = (const float*)d_in[5];
    const float* bias       = (const float*)d_in[6];
    float* out = (float*)d_out;

    feat_tr_kernel<<<FEAT_BLOCKS + TR_BLOCKS, K1_THREADS>>>(
        ngram_ids, ngram_mask, ctx_ids, ctx_mask, embed, W);
    gemm_kernel<<<(BB * SS) / GT, 192>>>(bias, out);
}

// round 3
// speedup vs baseline: 2.1370x; 1.3021x over previous
#include <cuda_runtime.h>

#define BB 32
#define SS 128
#define KN 12
#define KC 10
#define DD 200
#define D4 (DD/4)            // 50
#define CC 45
#define CP 48                // padded C
#define CP4 (CP/4)           // 12
#define FF (5*DD)            // 1000
#define NTOK (BB*SS)         // 4096

#define GT 32                // tokens per gemm tile
#define NTILES (NTOK/GT)     // 128
#define APAD 51              // shA row pitch in float4 (204 floats)

#define FEAT_BLOCKS NTOK
#define TR_ELEMS (FF*CP)                       // 48000
#define TR_BLOCKS ((TR_ELEMS + 63) / 64)       // 750

__device__ float g_feat[NTOK*DD];          // [tok, D]
__device__ float g_Wt[FF*CP];              // [k, 48] transposed+padded
__device__ float g_part[5*NTOK*CP];        // per-w partial sums [w, tok, 48]

// ---------------------------------------------------------------------------
// Kernel 1: masked float4 gather+mean (64-thr blocks, ~all resident in 1 wave)
//           + W transpose appended to the same grid.
// ---------------------------------------------------------------------------
__global__ void feat_tr_kernel(const int* __restrict__ ngram_ids,
                               const int* __restrict__ ngram_mask,
                               const int* __restrict__ ctx_ids,
                               const int* __restrict__ ctx_mask,
                               const float* __restrict__ embed,
                               const float* __restrict__ W) {
    if (blockIdx.x >= FEAT_BLOCKS) {
        int idx = (blockIdx.x - FEAT_BLOCKS) * 64 + threadIdx.x;
        if (idx < TR_ELEMS) {
            int c = idx / FF;
            int k = idx - c * FF;
            g_Wt[k * CP + c] = (c < CC) ? W[c * FF + k] : 0.0f;
        }
        return;
    }

    const int tok = blockIdx.x;
    const int tid = threadIdx.x;

    __shared__ int s_id[KN + KC];
    __shared__ int s_mk[KN + KC];

    if (tid < KN) {
        s_id[tid] = ngram_ids[tok * KN + tid];
        s_mk[tid] = ngram_mask[tok * KN + tid];
    } else if (tid < KN + KC) {
        int k = tid - KN;
        s_id[tid] = ctx_ids[tok * KC + k];
        s_mk[tid] = ctx_mask[tok * KC + k];
    }
    __syncthreads();

    if (tid >= D4) return;

    const float4* embed4 = (const float4*)embed;
    float ax = 0.f, ay = 0.f, az = 0.f, aw = 0.f;
    int cnt = 0;
    #pragma unroll
    for (int k = 0; k < KN + KC; k++) {
        if (s_mk[k]) {
            float4 e = embed4[(long long)s_id[k] * D4 + tid];
            ax += e.x; ay += e.y; az += e.z; aw += e.w;
            cnt++;
        }
    }
    float denom = cnt > 0 ? (float)cnt : 1.0f;
    float4 r;
    r.x = ax / denom; r.y = ay / denom; r.z = az / denom; r.w = aw / denom;
    ((float4*)g_feat)[tok * D4 + tid] = r;
}

// ---------------------------------------------------------------------------
// Kernel 2: per-window partial GEMM.  Grid (128 tiles, 5 w), 384 threads.
// Thread = 1 token x 4 c; warp = 16 tg x 2 adjacent cg:
//   per 4-k step: A: 1 LDS.128 (2 wf, padded rows) + B: 4 LDS.128 (broadcast)
//   + 16 FFMA  -> FMA-bound at ~75% crossbar.
// ---------------------------------------------------------------------------
__global__ void __launch_bounds__(384) gemm_kernel() {
    __shared__ float4 shA[GT * APAD];        // 26112 B (rows padded to 204 fl)
    __shared__ float4 shB[100 * CP4];        // 19200 B (half of a w-chunk)

    const int w = blockIdx.y;
    const int tokBase = blockIdx.x * GT;
    const int b  = tokBase / SS;
    const int s0 = tokBase % SS;

    const int tid = threadIdx.x;
    const int lane = tid & 31;
    const int upper = tid >> 5;              // 0..11
    const int tg = (lane & 15) + 16 * (upper & 1);
    const int cg = (upper >> 1) * 2 + (lane >> 4);   // 0..11

    // stage A: feat rows s0+w-2 .. s0+w+29 (zero halo), float4, padded pitch
    const float4* gf4 = (const float4*)g_feat;
    for (int i = tid; i < GT * D4; i += 384) {
        int r  = i / D4;
        int dv = i - r * D4;
        int s  = s0 + w - 2 + r;
        float4 v = make_float4(0.f, 0.f, 0.f, 0.f);
        if (s >= 0 && s < SS) v = gf4[(b * SS + s) * D4 + dv];
        shA[r * APAD + dv] = v;
    }

    float acc0 = 0.f, acc1 = 0.f, acc2 = 0.f, acc3 = 0.f;
    const float4* Wt4 = (const float4*)g_Wt;

    #pragma unroll
    for (int h = 0; h < 2; h++) {
        __syncthreads();
        // stage B rows [w*200 + h*100, +100)
        for (int i = tid; i < 100 * CP4; i += 384)
            shB[i] = Wt4[(w * DD + h * 100) * CP4 + i];
        __syncthreads();

        const float4* aRow = &shA[tg * APAD + h * 25];
        #pragma unroll
        for (int dq = 0; dq < 25; dq++) {
            float4 a  = aRow[dq];
            float4 b0 = shB[(dq * 4 + 0) * CP4 + cg];
            float4 b1 = shB[(dq * 4 + 1) * CP4 + cg];
            float4 b2 = shB[(dq * 4 + 2) * CP4 + cg];
            float4 b3 = shB[(dq * 4 + 3) * CP4 + cg];
            acc0 = fmaf(a.x, b0.x, acc0); acc1 = fmaf(a.x, b0.y, acc1);
            acc2 = fmaf(a.x, b0.z, acc2); acc3 = fmaf(a.x, b0.w, acc3);
            acc0 = fmaf(a.y, b1.x, acc0); acc1 = fmaf(a.y, b1.y, acc1);
            acc2 = fmaf(a.y, b1.z, acc2); acc3 = fmaf(a.y, b1.w, acc3);
            acc0 = fmaf(a.z, b2.x, acc0); acc1 = fmaf(a.z, b2.y, acc1);
            acc2 = fmaf(a.z, b2.z, acc2); acc3 = fmaf(a.z, b2.w, acc3);
            acc0 = fmaf(a.w, b3.x, acc0); acc1 = fmaf(a.w, b3.y, acc1);
            acc2 = fmaf(a.w, b3.z, acc2); acc3 = fmaf(a.w, b3.w, acc3);
        }
    }

    float4 v; v.x = acc0; v.y = acc1; v.z = acc2; v.w = acc3;
    ((float4*)g_part)[((long long)w * NTOK + tokBase + tg) * CP4 + cg] = v;
}

// ---------------------------------------------------------------------------
// Kernel 3: reduce 5 partials + bias -> out [tok, 45]
// ---------------------------------------------------------------------------
__global__ void reduce_kernel(const float* __restrict__ bias,
                              float* __restrict__ out) {
    int i = blockIdx.x * blockDim.x + threadIdx.x;
    if (i >= NTOK * CC) return;
    int tok = i / CC;
    int c   = i - tok * CC;
    float s = bias[c];
    #pragma unroll
    for (int w = 0; w < 5; w++)
        s += g_part[(w * NTOK + tok) * CP + c];
    out[i] = s;
}

// ---------------------------------------------------------------------------
// Inputs: 0 ngram_ids, 1 ngram_mask, 2 ctx_ids, 3 ctx_mask,
//         4 embed [V,200] f32, 5 W [45,1000] f32, 6 b [45] f32.
// Output [B,S,45] f32.
// ---------------------------------------------------------------------------
extern "C" void kernel_launch(void* const* d_in, const int* in_sizes, int n_in,
                              void* d_out, int out_size) {
    const int*   ngram_ids  = (const int*)d_in[0];
    const int*   ngram_mask = (const int*)d_in[1];
    const int*   ctx_ids    = (const int*)d_in[2];
    const int*   ctx_mask   = (const int*)d_in[3];
    const float* embed      = (const float*)d_in[4];
    const float* W          = (const float*)d_in[5];
    const float* bias       = (const float*)d_in[6];
    float* out = (float*)d_out;

    feat_tr_kernel<<<FEAT_BLOCKS + TR_BLOCKS, 64>>>(
        ngram_ids, ngram_mask, ctx_ids, ctx_mask, embed, W);
    gemm_kernel<<<dim3(NTILES, 5), 384>>>();
    reduce_kernel<<<(NTOK * CC + 255) / 256, 256>>>(bias, out);
}

// round 4
// speedup vs baseline: 2.2581x; 1.0567x over previous
#include <cuda_runtime.h>

#define BB 32
#define SS 128
#define KN 12
#define KC 10
#define KT (KN+KC)           // 22
#define DD 200
#define D4 (DD/4)            // 50
#define CC 45
#define CP 48
#define CP4 (CP/4)           // 12
#define FF (5*DD)            // 1000
#define NTOK (BB*SS)         // 4096

#define GT 32                // tokens per gemm tile
#define NTILES (NTOK/GT)     // 128
#define APAD 51              // shA row pitch in float4

#define FEAT_BLOCKS (NTOK/2)                   // 2048 (2 tokens/block)
#define TR_ELEMS (FF*CP)                       // 48000
#define TR_BLOCKS ((TR_ELEMS + 127) / 128)     // 375

__device__ float g_feat[NTOK*DD];          // [tok, D]
__device__ float g_Wt[FF*CP];              // [k, 48]
__device__ float g_part[5*NTOK*CP];        // [w, tok, 48]

// ---------------------------------------------------------------------------
// Kernel 1: masked gather+mean with ballot-compacted id list, 2 tokens/block.
// Reg-capped for full occupancy; dense unroll-4 load loop for MLP.
// W transpose appended to the same grid.
// ---------------------------------------------------------------------------
__global__ void __launch_bounds__(128, 16)
feat_tr_kernel(const int* __restrict__ ngram_ids,
               const int* __restrict__ ngram_mask,
               const int* __restrict__ ctx_ids,
               const int* __restrict__ ctx_mask,
               const float* __restrict__ embed,
               const float* __restrict__ W) {
    if (blockIdx.x >= FEAT_BLOCKS) {
        int idx = (blockIdx.x - FEAT_BLOCKS) * 128 + threadIdx.x;
        if (idx < TR_ELEMS) {
            int c = idx / FF;
            int k = idx - c * FF;
            g_Wt[k * CP + c] = (c < CC) ? W[c * FF + k] : 0.0f;
        }
        return;
    }

    const int half = threadIdx.x >> 6;            // token within block
    const int lane = threadIdx.x & 63;
    const int tok  = blockIdx.x * 2 + half;

    __shared__ int s_act[2][24];
    __shared__ int s_cnt[2];

    // warp 0 of each 64-thread group compacts active feature ids
    if (lane < 32) {
        int m = 0, id = 0;
        if (lane < KN) {
            id = ngram_ids[tok * KN + lane];
            m  = ngram_mask[tok * KN + lane];
        } else if (lane < KT) {
            id = ctx_ids[tok * KC + lane - KN];
            m  = ctx_mask[tok * KC + lane - KN];
        }
        unsigned bal = __ballot_sync(0xffffffffu, m != 0);
        if (m) {
            int pos = __popc(bal & ((1u << lane) - 1u));
            s_act[half][pos] = id;
        }
        if (lane == 0) s_cnt[half] = __popc(bal);
    }
    __syncthreads();

    if (lane >= D4) return;

    const int n = s_cnt[half];
    const int* act = s_act[half];
    const float4* e4 = (const float4*)embed;

    float ax = 0.f, ay = 0.f, az = 0.f, aw = 0.f;
    int j = 0;
    for (; j + 4 <= n; j += 4) {               // 4 independent LDG.128 in flight
        float4 a = e4[(long long)act[j + 0] * D4 + lane];
        float4 b = e4[(long long)act[j + 1] * D4 + lane];
        float4 c = e4[(long long)act[j + 2] * D4 + lane];
        float4 d = e4[(long long)act[j + 3] * D4 + lane];
        ax += (a.x + b.x) + (c.x + d.x);
        ay += (a.y + b.y) + (c.y + d.y);
        az += (a.z + b.z) + (c.z + d.z);
        aw += (a.w + b.w) + (c.w + d.w);
    }
    for (; j < n; j++) {
        float4 a = e4[(long long)act[j] * D4 + lane];
        ax += a.x; ay += a.y; az += a.z; aw += a.w;
    }

    float inv = 1.0f / (float)(n > 0 ? n : 1);
    float4 r; r.x = ax * inv; r.y = ay * inv; r.z = az * inv; r.w = aw * inv;
    ((float4*)g_feat)[tok * D4 + lane] = r;
}

// ---------------------------------------------------------------------------
// Kernel 2: per-window partial GEMM (unchanged from R3 — FMA-bound tile).
// ---------------------------------------------------------------------------
__global__ void __launch_bounds__(384) gemm_kernel() {
    __shared__ float4 shA[GT * APAD];
    __shared__ float4 shB[100 * CP4];

    const int w = blockIdx.y;
    const int tokBase = blockIdx.x * GT;
    const int b  = tokBase / SS;
    const int s0 = tokBase % SS;

    const int tid = threadIdx.x;
    const int lane = tid & 31;
    const int upper = tid >> 5;
    const int tg = (lane & 15) + 16 * (upper & 1);
    const int cg = (upper >> 1) * 2 + (lane >> 4);

    const float4* gf4 = (const float4*)g_feat;
    for (int i = tid; i < GT * D4; i += 384) {
        int r  = i / D4;
        int dv = i - r * D4;
        int s  = s0 + w - 2 + r;
        float4 v = make_float4(0.f, 0.f, 0.f, 0.f);
        if (s >= 0 && s < SS) v = gf4[(b * SS + s) * D4 + dv];
        shA[r * APAD + dv] = v;
    }

    float acc0 = 0.f, acc1 = 0.f, acc2 = 0.f, acc3 = 0.f;
    const float4* Wt4 = (const float4*)g_Wt;

    #pragma unroll
    for (int h = 0; h < 2; h++) {
        __syncthreads();
        for (int i = tid; i < 100 * CP4; i += 384)
            shB[i] = Wt4[(w * DD + h * 100) * CP4 + i];
        __syncthreads();

        const float4* aRow = &shA[tg * APAD + h * 25];
        #pragma unroll
        for (int dq = 0; dq < 25; dq++) {
            float4 a  = aRow[dq];
            float4 b0 = shB[(dq * 4 + 0) * CP4 + cg];
            float4 b1 = shB[(dq * 4 + 1) * CP4 + cg];
            float4 b2 = shB[(dq * 4 + 2) * CP4 + cg];
            float4 b3 = shB[(dq * 4 + 3) * CP4 + cg];
            acc0 = fmaf(a.x, b0.x, acc0); acc1 = fmaf(a.x, b0.y, acc1);
            acc2 = fmaf(a.x, b0.z, acc2); acc3 = fmaf(a.x, b0.w, acc3);
            acc0 = fmaf(a.y, b1.x, acc0); acc1 = fmaf(a.y, b1.y, acc1);
            acc2 = fmaf(a.y, b1.z, acc2); acc3 = fmaf(a.y, b1.w, acc3);
            acc0 = fmaf(a.z, b2.x, acc0); acc1 = fmaf(a.z, b2.y, acc1);
            acc2 = fmaf(a.z, b2.z, acc2); acc3 = fmaf(a.z, b2.w, acc3);
            acc0 = fmaf(a.w, b3.x, acc0); acc1 = fmaf(a.w, b3.y, acc1);
            acc2 = fmaf(a.w, b3.z, acc2); acc3 = fmaf(a.w, b3.w, acc3);
        }
    }

    float4 v; v.x = acc0; v.y = acc1; v.z = acc2; v.w = acc3;
    ((float4*)g_part)[((long long)w * NTOK + tokBase + tg) * CP4 + cg] = v;
}

// ---------------------------------------------------------------------------
// Kernel 3: reduce 5 partials (float4) + bias -> out [tok, 45]
// ---------------------------------------------------------------------------
__global__ void reduce_kernel(const float* __restrict__ bias,
                              float* __restrict__ out) {
    int i = blockIdx.x * blockDim.x + threadIdx.x;
    if (i >= NTOK * CP4) return;
    int tok = i / CP4;
    int cg  = i - tok * CP4;
    const float4* p4 = (const float4*)g_part;
    float4 s = make_float4(0.f, 0.f, 0.f, 0.f);
    #pragma unroll
    for (int w = 0; w < 5; w++) {
        float4 v = p4[((long long)w * NTOK + tok) * CP4 + cg];
        s.x += v.x; s.y += v.y; s.z += v.z; s.w += v.w;
    }
    int c0 = cg * 4;
    float* o = out + (long long)tok * CC;
    if (c0 + 0 < CC) o[c0 + 0] = s.x + bias[c0 + 0];
    if (c0 + 1 < CC) o[c0 + 1] = s.y + bias[c0 + 1];
    if (c0 + 2 < CC) o[c0 + 2] = s.z + bias[c0 + 2];
    if (c0 + 3 < CC) o[c0 + 3] = s.w + bias[c0 + 3];
}

// ---------------------------------------------------------------------------
extern "C" void kernel_launch(void* const* d_in, const int* in_sizes, int n_in,
                              void* d_out, int out_size) {
    const int*   ngram_ids  = (const int*)d_in[0];
    const int*   ngram_mask = (const int*)d_in[1];
    const int*   ctx_ids    = (const int*)d_in[2];
    const int*   ctx_mask   = (const int*)d_in[3];
    const float* embed      = (const float*)d_in[4];
    const float* W          = (const float*)d_in[5];
    const float* bias       = (const float*)d_in[6];
    float* out = (float*)d_out;

    feat_tr_kernel<<<FEAT_BLOCKS + TR_BLOCKS, 128>>>(
        ngram_ids, ngram_mask, ctx_ids, ctx_mask, embed, W);
    gemm_kernel<<<dim3(NTILES, 5), 384>>>();
    reduce_kernel<<<(NTOK * CP4 + 255) / 256, 256>>>(bias, out);
}